// round 1
// baseline (speedup 1.0000x reference)
#include <cuda_runtime.h>
#include <cuda_bf16.h>

#define IMG_W 1024
#define IMG_H 1024
#define NC_TOTAL 48   // 16 batch * 3 channels

// Each thread computes 4 consecutive output pixels in one row (float4 in/out).
// num = depthwise corr(x, w/||w||), den = sqrt(corr(x^2, ones3x3)); out = num * rsqrt(den^2).
__global__ void __launch_bounds__(256) normconv3x3_kernel(
    const float* __restrict__ x,
    const float* __restrict__ wt,
    float* __restrict__ out)
{
    int tid = blockIdx.x * blockDim.x + threadIdx.x;
    // layout: tid -> (nc, y, x4group); 256 groups of 4 per row
    int x0 = (tid & 255) << 2;          // 0..1020 step 4
    int y  = (tid >> 8) & 1023;
    int nc = tid >> 18;                 // 0..47
    int c  = nc % 3;

    // Per-channel normalized 3x3 weights (27-float broadcast, const-cache hit)
    float w[9];
    float s2 = 0.f;
#pragma unroll
    for (int k = 0; k < 9; k++) { w[k] = __ldg(&wt[c * 9 + k]); s2 += w[k] * w[k]; }
    float winv = rsqrtf(s2);
#pragma unroll
    for (int k = 0; k < 9; k++) w[k] *= winv;

    const float* base = x + ((size_t)nc << 20) + (size_t)y * IMG_W + x0;

    float num0 = 0.f, num1 = 0.f, num2 = 0.f, num3 = 0.f;
    float sq0  = 0.f, sq1  = 0.f, sq2  = 0.f, sq3  = 0.f;

#pragma unroll
    for (int r = 0; r < 3; r++) {
        int yy = y + r - 1;
        bool rvalid = (yy >= 0) & (yy < IMG_H);
        const float* rp = base + (r - 1) * IMG_W;

        float a0 = 0.f, a1 = 0.f, a2 = 0.f, a3 = 0.f, a4 = 0.f, a5 = 0.f;
        if (rvalid) {
            float4 v = *reinterpret_cast<const float4*>(rp);
            a1 = v.x; a2 = v.y; a3 = v.z; a4 = v.w;
            if (x0 > 0)         a0 = __ldg(rp - 1);
            if (x0 < IMG_W - 4) a5 = __ldg(rp + 4);
        }

        float w0 = w[r * 3 + 0], w1 = w[r * 3 + 1], w2 = w[r * 3 + 2];
        num0 = fmaf(w0, a0, fmaf(w1, a1, fmaf(w2, a2, num0)));
        num1 = fmaf(w0, a1, fmaf(w1, a2, fmaf(w2, a3, num1)));
        num2 = fmaf(w0, a2, fmaf(w1, a3, fmaf(w2, a4, num2)));
        num3 = fmaf(w0, a3, fmaf(w1, a4, fmaf(w2, a5, num3)));

        sq0 = fmaf(a0, a0, fmaf(a1, a1, fmaf(a2, a2, sq0)));
        sq1 = fmaf(a1, a1, fmaf(a2, a2, fmaf(a3, a3, sq1)));
        sq2 = fmaf(a2, a2, fmaf(a3, a3, fmaf(a4, a4, sq2)));
        sq3 = fmaf(a3, a3, fmaf(a4, a4, fmaf(a5, a5, sq3)));
    }

    float4 o;
    o.x = num0 * rsqrtf(sq0);
    o.y = num1 * rsqrtf(sq1);
    o.z = num2 * rsqrtf(sq2);
    o.w = num3 * rsqrtf(sq3);

    *reinterpret_cast<float4*>(out + ((size_t)nc << 20) + (size_t)y * IMG_W + x0) = o;
}

extern "C" void kernel_launch(void* const* d_in, const int* in_sizes, int n_in,
                              void* d_out, int out_size) {
    const float* x  = (const float*)d_in[0];
    const float* wt = (const float*)d_in[1];
    float* out = (float*)d_out;

    // total threads: 48 nc * 1024 rows * 256 quad-groups = 12,582,912
    const int total = NC_TOTAL * IMG_H * (IMG_W / 4);
    const int block = 256;
    const int grid = total / block;  // 49152
    normconv3x3_kernel<<<grid, block>>>(x, wt, out);
}